// round 11
// baseline (speedup 1.0000x reference)
#include <cuda_runtime.h>
#include <cuda_fp16.h>
#include <cstdint>

#define NN 100000
#define NF 512
#define NH 256
#define NC 40
#define ECAP 1700000
#define CAP 96           // ELL max degree (true max ~45)

// ---------------- scratch (device-side access only) ----------------
__device__ __half2 d_XWh2[(size_t)NN * (NH / 2)];  // x@W1 in fp16 (51.2 MB)
__device__ float   d_H [(size_t)NN * NH];          // relu(A·XW + b1) (102.4 MB)
__device__ float   d_HW[(size_t)NN * NC];          // H @ W2 (16 MB)
__device__ int     d_deg[NN];                      // ELL per-row cursor
__device__ int     d_ecol[(size_t)NN * CAP];       // ELL columns (38.4 MB)
__device__ float   d_eval[(size_t)NN * CAP];       // ELL values  (38.4 MB)

// ---------------- zero + ELL build ----------------
__global__ void k_zero() {
    int i = blockIdx.x * blockDim.x + threadIdx.x;
    if (i < NN) d_deg[i] = 0;
}

__global__ void k_ell(const int* __restrict__ er, const int* __restrict__ ec,
                      const float* __restrict__ ev, int E) {
    int i = blockIdx.x * blockDim.x + threadIdx.x;
    if (i >= E) return;
    int r = er[i];
    int slot = atomicAdd(&d_deg[r], 1);
    if (slot < CAP) {
        d_ecol[(size_t)r * CAP + slot] = ec[i];
        d_eval[(size_t)r * CAP + slot] = ev[i];
    }
}

// ---------------- GEMM1 (fp16 mma, fused fp32->fp16 convert) ----------------
// 128x256 block tile (full N -> X read ONCE), 512 threads / 16 warps,
// warp tile 32x64 (4m x 4n), BK=32, mma.m16n8k16.f16 with fp32 accum.
// Register double-buffered staging (LDG fp32 -> cvt_rn -> STS fp16).
// Smem rows padded to 40 halfs: MMA-read bank = (20*gid + tig) mod 32,
// all 32 lanes distinct -> conflict-free.
__global__ __launch_bounds__(512) void k_gemm1(const float* __restrict__ X,
                                               const float* __restrict__ W1) {
    __shared__ __half As[128][40];    // A tile,  m-major [m][k]
    __shared__ __half Bt[256][40];    // B tile, n-major [n][k] (transposed)

    const int tid  = threadIdx.x;
    const int lane = tid & 31;
    const int wid  = tid >> 5;
    const int wm   = wid & 3;         // 4 m-warps * 32 rows
    const int wn   = wid >> 2;        // 4 n-warps * 64 cols
    const int gid  = lane >> 2;
    const int tig  = lane & 3;
    const int m0   = blockIdx.x * 128;

    float acc[2][8][4];
#pragma unroll
    for (int mf = 0; mf < 2; mf++)
#pragma unroll
        for (int nf = 0; nf < 8; nf++)
#pragma unroll
            for (int c = 0; c < 4; c++) acc[mf][nf][c] = 0.f;

    float4 ra[2], rb[4];

    auto loadreg = [&](int k0) {
#pragma unroll
        for (int p = 0; p < 2; p++) {
            int i = p * 512 + tid;
            int m = i >> 3, j = i & 7;
            int row = m0 + m;
            row = row < NN ? row : NN - 1;     // clamp; OOB rows never stored
            ra[p] = *(const float4*)(X + (size_t)row * NF + k0 + j * 4);
        }
#pragma unroll
        for (int p = 0; p < 4; p++) {
            int i = p * 512 + tid;
            int k = i >> 6, j = i & 63;
            rb[p] = *(const float4*)(W1 + (size_t)(k0 + k) * NH + j * 4);
        }
    };

    auto storesm = [&]() {
#pragma unroll
        for (int p = 0; p < 2; p++) {
            int i = p * 512 + tid;
            int m = i >> 3, j = i & 7;
            __half2 h01 = __floats2half2_rn(ra[p].x, ra[p].y);
            __half2 h23 = __floats2half2_rn(ra[p].z, ra[p].w);
            *(__half2*)&As[m][j * 4]     = h01;
            *(__half2*)&As[m][j * 4 + 2] = h23;
        }
#pragma unroll
        for (int p = 0; p < 4; p++) {
            int i = p * 512 + tid;
            int k = i >> 6, j = i & 63;
            Bt[j * 4 + 0][k] = __float2half_rn(rb[p].x);
            Bt[j * 4 + 1][k] = __float2half_rn(rb[p].y);
            Bt[j * 4 + 2][k] = __float2half_rn(rb[p].z);
            Bt[j * 4 + 3][k] = __float2half_rn(rb[p].w);
        }
    };

    loadreg(0);

    const int NT = NF / 32;   // 16
    for (int t = 0; t < NT; t++) {
        __syncthreads();      // previous tile's MMA reads done
        storesm();
        __syncthreads();
        if (t + 1 < NT) loadreg(32 * (t + 1));   // LDG overlaps MMA below

#pragma unroll
        for (int ks = 0; ks < 2; ks++) {
            const int kc = ks * 16 + 2 * tig;
            uint32_t a[2][4];
#pragma unroll
            for (int mf = 0; mf < 2; mf++) {
                int mr = wm * 32 + mf * 16 + gid;
                a[mf][0] = *(const uint32_t*)&As[mr    ][kc    ];
                a[mf][1] = *(const uint32_t*)&As[mr + 8][kc    ];
                a[mf][2] = *(const uint32_t*)&As[mr    ][kc + 8];
                a[mf][3] = *(const uint32_t*)&As[mr + 8][kc + 8];
            }
#pragma unroll
            for (int nf = 0; nf < 8; nf++) {
                int nn = wn * 64 + nf * 8 + gid;
                uint32_t b0 = *(const uint32_t*)&Bt[nn][kc    ];
                uint32_t b1 = *(const uint32_t*)&Bt[nn][kc + 8];
#pragma unroll
                for (int mf = 0; mf < 2; mf++) {
                    asm volatile(
                        "mma.sync.aligned.m16n8k16.row.col.f32.f16.f16.f32 "
                        "{%0,%1,%2,%3}, {%4,%5,%6,%7}, {%8,%9}, {%0,%1,%2,%3};\n"
                        : "+f"(acc[mf][nf][0]), "+f"(acc[mf][nf][1]),
                          "+f"(acc[mf][nf][2]), "+f"(acc[mf][nf][3])
                        : "r"(a[mf][0]), "r"(a[mf][1]), "r"(a[mf][2]), "r"(a[mf][3]),
                          "r"(b0), "r"(b1));
                }
            }
        }
    }

    // epilogue: c0,c1 -> (row, 2tig..2tig+1); c2,c3 -> row+8. col even -> half2.
#pragma unroll
    for (int mf = 0; mf < 2; mf++) {
#pragma unroll
        for (int nf = 0; nf < 8; nf++) {
            int row = m0 + wm * 32 + mf * 16 + gid;
            int col = wn * 64 + nf * 8 + 2 * tig;
            if (row < NN) {
                d_XWh2[(size_t)row * (NH / 2) + (col >> 1)] =
                    __floats2half2_rn(acc[mf][nf][0], acc[mf][nf][1]);
            }
            if (row + 8 < NN) {
                d_XWh2[(size_t)(row + 8) * (NH / 2) + (col >> 1)] =
                    __floats2half2_rn(acc[mf][nf][2], acc[mf][nf][3]);
            }
        }
    }
}

// ---------------- SpMM1: d_H = relu(A @ XWh + b1) ----------------
__global__ __launch_bounds__(256) void k_spmm1(const float* __restrict__ b1) {
    __shared__ int   sc[2][CAP];
    __shared__ float sv[2][CAP];
    const int t   = threadIdx.x;
    const int g   = t >> 7;
    const int tf  = t & 127;
    const int row = blockIdx.x * 2 + g;
    if (row >= NN) return;

    int cnt = d_deg[row];
    cnt = cnt < CAP ? cnt : CAP;

    for (int j = tf; j < cnt; j += 128) {
        sc[g][j] = d_ecol[(size_t)row * CAP + j];
        sv[g][j] = d_eval[(size_t)row * CAP + j];
    }
    __syncthreads();

    float ax = 0.f, ay = 0.f;
    int j = 0;
    for (; j + 4 <= cnt; j += 4) {
        int   c0 = sc[g][j],     c1 = sc[g][j + 1];
        int   c2 = sc[g][j + 2], c3 = sc[g][j + 3];
        float v0 = sv[g][j],     v1 = sv[g][j + 1];
        float v2 = sv[g][j + 2], v3 = sv[g][j + 3];
        float2 f0 = __half22float2(d_XWh2[(size_t)c0 * 128 + tf]);
        float2 f1 = __half22float2(d_XWh2[(size_t)c1 * 128 + tf]);
        float2 f2 = __half22float2(d_XWh2[(size_t)c2 * 128 + tf]);
        float2 f3 = __half22float2(d_XWh2[(size_t)c3 * 128 + tf]);
        ax += v0 * f0.x; ay += v0 * f0.y;
        ax += v1 * f1.x; ay += v1 * f1.y;
        ax += v2 * f2.x; ay += v2 * f2.y;
        ax += v3 * f3.x; ay += v3 * f3.y;
    }
    for (; j < cnt; j++) {
        int   c = sc[g][j];
        float v = sv[g][j];
        float2 f = __half22float2(d_XWh2[(size_t)c * 128 + tf]);
        ax += v * f.x; ay += v * f.y;
    }

    float2 bb = *(const float2*)(b1 + 2 * tf);
    float2 o;
    o.x = fmaxf(ax + bb.x, 0.f);
    o.y = fmaxf(ay + bb.y, 0.f);
    __stcs((float2*)(d_H + (size_t)row * NH + 2 * tf), o);
}

// ---------------- GEMM2: d_HW = d_H @ W2 (2 rows/thread) ----------------
__global__ __launch_bounds__(256) void k_gemm2(const float* __restrict__ W2) {
    __shared__ float w2s[NH * NC];   // 40 KB
    for (int i = threadIdx.x; i < NH * NC; i += 256) w2s[i] = W2[i];
    __syncthreads();
    int r0 = blockIdx.x * 512 + threadIdx.x;
    int r1 = r0 + 256;
    if (r0 >= NN) return;
    bool two = (r1 < NN);
    float acc0[NC], acc1[NC];
#pragma unroll
    for (int c = 0; c < NC; c++) { acc0[c] = 0.f; acc1[c] = 0.f; }
    const float4* hp0 = (const float4*)(d_H + (size_t)r0 * NH);
    const float4* hp1 = (const float4*)(d_H + (size_t)(two ? r1 : r0) * NH);
#pragma unroll 2
    for (int k4 = 0; k4 < NH / 4; k4++) {
        float4 h0 = hp0[k4];
        float4 h1 = hp1[k4];
        float hv0[4] = {h0.x, h0.y, h0.z, h0.w};
        float hv1[4] = {h1.x, h1.y, h1.z, h1.w};
#pragma unroll
        for (int kk = 0; kk < 4; kk++) {
            const float* wrow = &w2s[(k4 * 4 + kk) * NC];
#pragma unroll
            for (int c4 = 0; c4 < NC / 4; c4++) {
                float4 wv = *(const float4*)(wrow + c4 * 4);
                acc0[c4 * 4 + 0] += hv0[kk] * wv.x;
                acc0[c4 * 4 + 1] += hv0[kk] * wv.y;
                acc0[c4 * 4 + 2] += hv0[kk] * wv.z;
                acc0[c4 * 4 + 3] += hv0[kk] * wv.w;
                acc1[c4 * 4 + 0] += hv1[kk] * wv.x;
                acc1[c4 * 4 + 1] += hv1[kk] * wv.y;
                acc1[c4 * 4 + 2] += hv1[kk] * wv.z;
                acc1[c4 * 4 + 3] += hv1[kk] * wv.w;
            }
        }
    }
    float* o0 = d_HW + (size_t)r0 * NC;
#pragma unroll
    for (int c4 = 0; c4 < NC / 4; c4++)
        *(float4*)(o0 + c4 * 4) = make_float4(acc0[c4 * 4], acc0[c4 * 4 + 1],
                                              acc0[c4 * 4 + 2], acc0[c4 * 4 + 3]);
    if (two) {
        float* o1 = d_HW + (size_t)r1 * NC;
#pragma unroll
        for (int c4 = 0; c4 < NC / 4; c4++)
            *(float4*)(o1 + c4 * 4) = make_float4(acc1[c4 * 4], acc1[c4 * 4 + 1],
                                                  acc1[c4 * 4 + 2], acc1[c4 * 4 + 3]);
    }
}

// ---------------- SpMM2: out = A @ d_HW + b2, warp per row (ELL) ----------------
__global__ __launch_bounds__(256) void k_spmm2(const float* __restrict__ b2,
                                               float* __restrict__ out) {
    int w = (blockIdx.x * blockDim.x + threadIdx.x) >> 5;
    int lane = threadIdx.x & 31;
    if (w >= NN) return;
    int cnt = d_deg[w];
    cnt = cnt < CAP ? cnt : CAP;
    const int*   cp = d_ecol + (size_t)w * CAP;
    const float* vp = d_eval + (size_t)w * CAP;
    float a0 = 0.f, a1 = 0.f;
    int i = 0;
    for (; i + 2 <= cnt; i += 2) {
        int   c0 = cp[i],   c1 = cp[i + 1];
        float v0 = vp[i],   v1 = vp[i + 1];
        const float* p0 = d_HW + (size_t)c0 * NC;
        const float* p1 = d_HW + (size_t)c1 * NC;
        float x0 = p0[lane];
        float x1 = p1[lane];
        float y0 = 0.f, y1 = 0.f;
        if (lane < 8) { y0 = p0[lane + 32]; y1 = p1[lane + 32]; }
        a0 += v0 * x0 + v1 * x1;
        a1 += v0 * y0 + v1 * y1;
    }
    if (i < cnt) {
        int   c = cp[i];
        float v = vp[i];
        const float* p = d_HW + (size_t)c * NC;
        a0 += v * p[lane];
        if (lane < 8) a1 += v * p[lane + 32];
    }
    float* o = out + (size_t)w * NC;
    o[lane] = a0 + b2[lane];
    if (lane < 8) o[lane + 32] = a1 + b2[lane + 32];
}

// ---------------- launch ----------------
extern "C" void kernel_launch(void* const* d_in, const int* in_sizes, int n_in,
                              void* d_out, int out_size) {
    const float* x   = (const float*)d_in[0];
    const float* W1  = (const float*)d_in[1];
    const float* b1  = (const float*)d_in[2];
    const float* W2  = (const float*)d_in[3];
    const float* b2  = (const float*)d_in[4];
    const int*   er  = (const int*)d_in[5];
    const int*   ec  = (const int*)d_in[6];
    const float* ev  = (const float*)d_in[7];
    int E = in_sizes[5];
    if (E > ECAP) E = ECAP;
    float* out = (float*)d_out;

    // kernel launch order: k_spmm1 at kernel index 3 (the profiled slot).
    k_gemm1<<<(NN + 127) / 128, 512>>>(x, W1);               // k0 (independent)
    k_zero<<<(NN + 511) / 512, 512>>>();                     // k1
    k_ell<<<(E + 255) / 256, 256>>>(er, ec, ev, E);          // k2
    k_spmm1<<<(NN + 1) / 2, 256>>>(b1);                      // k3 <- PROFILED
    k_gemm2<<<(NN + 511) / 512, 256>>>(W2);                  // k4
    k_spmm2<<<(NN * 32 + 255) / 256, 256>>>(b2, out);        // k5
}

// round 12
// speedup vs baseline: 2.2841x; 2.2841x over previous
#include <cuda_runtime.h>
#include <cuda_fp16.h>
#include <cstdint>

#define NN 100000
#define NF 512
#define NH 256
#define NC 40
#define ECAP 1700000
#define CAP 96           // ELL max degree (true max ~45)

// ---------------- scratch (device-side access only) ----------------
__device__ __half2 d_XWh2[(size_t)NN * (NH / 2)];  // x@W1 in fp16 (51.2 MB)
__device__ __half  d_W1h[(size_t)NH * NF];         // W1^T in fp16 [n][k] (256 KB)
__device__ float   d_H [(size_t)NN * NH];          // relu(A·XW + b1) (102.4 MB)
__device__ float   d_HW[(size_t)NN * NC];          // H @ W2 (16 MB)
__device__ int     d_deg[NN];                      // ELL per-row cursor
__device__ int     d_ecol[(size_t)NN * CAP];       // ELL columns (38.4 MB)
__device__ float   d_eval[(size_t)NN * CAP];       // ELL values  (38.4 MB)

// ---------------- zero + ELL build + W1 transpose ----------------
__global__ void k_zero() {
    int i = blockIdx.x * blockDim.x + threadIdx.x;
    if (i < NN) d_deg[i] = 0;
}

__global__ void k_ell(const int* __restrict__ er, const int* __restrict__ ec,
                      const float* __restrict__ ev, int E) {
    int i = blockIdx.x * blockDim.x + threadIdx.x;
    if (i >= E) return;
    int r = er[i];
    int slot = atomicAdd(&d_deg[r], 1);
    if (slot < CAP) {
        d_ecol[(size_t)r * CAP + slot] = ec[i];
        d_eval[(size_t)r * CAP + slot] = ev[i];
    }
}

// one-time: d_W1h[n][k] = fp16(W1[k][n])   (131072 elems)
__global__ void k_prep(const float* __restrict__ W1) {
    int i = blockIdx.x * 256 + threadIdx.x;
    if (i < NF * NH) {
        int k = i >> 8;        // NH = 256
        int n = i & 255;
        d_W1h[n * NF + k] = __float2half_rn(W1[i]);
    }
}

// ---------------- GEMM1 (fp16 mma): XWh = fp16(x @ W1) ----------------
// 128x256 block tile (full N -> X read ONCE), 512 threads / 16 warps,
// warp tile 32x64, BK=32, mma.m16n8k16.f16 fp32-accum.
// A staged fp32->fp16 in registers; B staged from pre-transposed d_W1h with
// plain 16B copies (conflict-free). Rows padded to 40 halfs ->
// MMA-read bank = (20*gid + tig + 8ks) mod 32, all lanes distinct.
__global__ __launch_bounds__(512) void k_gemm1(const float* __restrict__ X) {
    __shared__ __half As[128][40];    // [m][k]
    __shared__ __half Bt[256][40];    // [n][k]

    const int tid  = threadIdx.x;
    const int lane = tid & 31;
    const int wid  = tid >> 5;
    const int wm   = wid & 3;
    const int wn   = wid >> 2;
    const int gid  = lane >> 2;
    const int tig  = lane & 3;
    const int m0   = blockIdx.x * 128;

    float acc[2][8][4];
#pragma unroll
    for (int mf = 0; mf < 2; mf++)
#pragma unroll
        for (int nf = 0; nf < 8; nf++)
#pragma unroll
            for (int c = 0; c < 4; c++) acc[mf][nf][c] = 0.f;

    float4 ra[2];
    uint4  rb[2];

    auto loadreg = [&](int k0) {
#pragma unroll
        for (int p = 0; p < 2; p++) {
            int i = p * 512 + tid;
            int m = i >> 3, j = i & 7;
            int row = m0 + m;
            row = row < NN ? row : NN - 1;     // clamp; OOB rows never stored
            ra[p] = *(const float4*)(X + (size_t)row * NF + k0 + j * 4);
        }
#pragma unroll
        for (int p = 0; p < 2; p++) {
            int i = p * 512 + tid;
            int n = i >> 2, q = i & 3;         // 16B chunk q of row n
            rb[p] = *(const uint4*)(d_W1h + n * NF + k0 + q * 8);
        }
    };

    auto storesm = [&]() {
#pragma unroll
        for (int p = 0; p < 2; p++) {
            int i = p * 512 + tid;
            int m = i >> 3, j = i & 7;
            *(__half2*)&As[m][j * 4]     = __floats2half2_rn(ra[p].x, ra[p].y);
            *(__half2*)&As[m][j * 4 + 2] = __floats2half2_rn(ra[p].z, ra[p].w);
        }
#pragma unroll
        for (int p = 0; p < 2; p++) {
            int i = p * 512 + tid;
            int n = i >> 2, q = i & 3;
            *(uint4*)&Bt[n][q * 8] = rb[p];    // 16B aligned (80*n + 16*q)
        }
    };

    loadreg(0);

    const int NT = NF / 32;   // 16
    for (int t = 0; t < NT; t++) {
        __syncthreads();
        storesm();
        __syncthreads();
        if (t + 1 < NT) loadreg(32 * (t + 1));   // LDG overlaps MMAs below

#pragma unroll
        for (int ks = 0; ks < 2; ks++) {
            const int kc = ks * 16 + 2 * tig;
            uint32_t a[2][4];
#pragma unroll
            for (int mf = 0; mf < 2; mf++) {
                int mr = wm * 32 + mf * 16 + gid;
                a[mf][0] = *(const uint32_t*)&As[mr    ][kc    ];
                a[mf][1] = *(const uint32_t*)&As[mr + 8][kc    ];
                a[mf][2] = *(const uint32_t*)&As[mr    ][kc + 8];
                a[mf][3] = *(const uint32_t*)&As[mr + 8][kc + 8];
            }
#pragma unroll
            for (int nf = 0; nf < 8; nf++) {
                int nn = wn * 64 + nf * 8 + gid;
                uint32_t b0 = *(const uint32_t*)&Bt[nn][kc    ];
                uint32_t b1 = *(const uint32_t*)&Bt[nn][kc + 8];
#pragma unroll
                for (int mf = 0; mf < 2; mf++) {
                    asm volatile(
                        "mma.sync.aligned.m16n8k16.row.col.f32.f16.f16.f32 "
                        "{%0,%1,%2,%3}, {%4,%5,%6,%7}, {%8,%9}, {%0,%1,%2,%3};\n"
                        : "+f"(acc[mf][nf][0]), "+f"(acc[mf][nf][1]),
                          "+f"(acc[mf][nf][2]), "+f"(acc[mf][nf][3])
                        : "r"(a[mf][0]), "r"(a[mf][1]), "r"(a[mf][2]), "r"(a[mf][3]),
                          "r"(b0), "r"(b1));
                }
            }
        }
    }

    // epilogue: c0,c1 -> (row, 2tig..+1); c2,c3 -> row+8. col even -> half2.
#pragma unroll
    for (int mf = 0; mf < 2; mf++) {
#pragma unroll
        for (int nf = 0; nf < 8; nf++) {
            int row = m0 + wm * 32 + mf * 16 + gid;
            int col = wn * 64 + nf * 8 + 2 * tig;
            if (row < NN) {
                d_XWh2[(size_t)row * (NH / 2) + (col >> 1)] =
                    __floats2half2_rn(acc[mf][nf][0], acc[mf][nf][1]);
            }
            if (row + 8 < NN) {
                d_XWh2[(size_t)(row + 8) * (NH / 2) + (col >> 1)] =
                    __floats2half2_rn(acc[mf][nf][2], acc[mf][nf][3]);
            }
        }
    }
}

// ---------------- SpMM1: d_H = relu(A @ XWh + b1) ----------------
__global__ __launch_bounds__(256) void k_spmm1(const float* __restrict__ b1) {
    __shared__ int   sc[2][CAP];
    __shared__ float sv[2][CAP];
    const int t   = threadIdx.x;
    const int g   = t >> 7;
    const int tf  = t & 127;
    const int row = blockIdx.x * 2 + g;
    if (row >= NN) return;

    int cnt = d_deg[row];
    cnt = cnt < CAP ? cnt : CAP;

    for (int j = tf; j < cnt; j += 128) {
        sc[g][j] = d_ecol[row * CAP + j];      // row*CAP < 9.6M: int ok
        sv[g][j] = d_eval[row * CAP + j];
    }
    __syncthreads();

    float ax = 0.f, ay = 0.f;
    int j = 0;
    for (; j + 4 <= cnt; j += 4) {
        int   c0 = sc[g][j],     c1 = sc[g][j + 1];
        int   c2 = sc[g][j + 2], c3 = sc[g][j + 3];
        float v0 = sv[g][j],     v1 = sv[g][j + 1];
        float v2 = sv[g][j + 2], v3 = sv[g][j + 3];
        // int index: c*128+tf < 12.8M, fits easily
        float2 f0 = __half22float2(d_XWh2[(c0 << 7) + tf]);
        float2 f1 = __half22float2(d_XWh2[(c1 << 7) + tf]);
        float2 f2 = __half22float2(d_XWh2[(c2 << 7) + tf]);
        float2 f3 = __half22float2(d_XWh2[(c3 << 7) + tf]);
        ax += v0 * f0.x; ay += v0 * f0.y;
        ax += v1 * f1.x; ay += v1 * f1.y;
        ax += v2 * f2.x; ay += v2 * f2.y;
        ax += v3 * f3.x; ay += v3 * f3.y;
    }
    for (; j < cnt; j++) {
        int   c = sc[g][j];
        float v = sv[g][j];
        float2 f = __half22float2(d_XWh2[(c << 7) + tf]);
        ax += v * f.x; ay += v * f.y;
    }

    float2 bb = *(const float2*)(b1 + 2 * tf);
    float2 o;
    o.x = fmaxf(ax + bb.x, 0.f);
    o.y = fmaxf(ay + bb.y, 0.f);
    __stcs((float2*)(d_H + (size_t)row * NH + 2 * tf), o);
}

// ---------------- GEMM2: d_HW = d_H @ W2 (2 rows/thread) ----------------
__global__ __launch_bounds__(256) void k_gemm2(const float* __restrict__ W2) {
    __shared__ float w2s[NH * NC];   // 40 KB
    for (int i = threadIdx.x; i < NH * NC; i += 256) w2s[i] = W2[i];
    __syncthreads();
    int r0 = blockIdx.x * 512 + threadIdx.x;
    int r1 = r0 + 256;
    if (r0 >= NN) return;
    bool two = (r1 < NN);
    float acc0[NC], acc1[NC];
#pragma unroll
    for (int c = 0; c < NC; c++) { acc0[c] = 0.f; acc1[c] = 0.f; }
    const float4* hp0 = (const float4*)(d_H + (size_t)r0 * NH);
    const float4* hp1 = (const float4*)(d_H + (size_t)(two ? r1 : r0) * NH);
#pragma unroll 2
    for (int k4 = 0; k4 < NH / 4; k4++) {
        float4 h0 = hp0[k4];
        float4 h1 = hp1[k4];
        float hv0[4] = {h0.x, h0.y, h0.z, h0.w};
        float hv1[4] = {h1.x, h1.y, h1.z, h1.w};
#pragma unroll
        for (int kk = 0; kk < 4; kk++) {
            const float* wrow = &w2s[(k4 * 4 + kk) * NC];
#pragma unroll
            for (int c4 = 0; c4 < NC / 4; c4++) {
                float4 wv = *(const float4*)(wrow + c4 * 4);
                acc0[c4 * 4 + 0] += hv0[kk] * wv.x;
                acc0[c4 * 4 + 1] += hv0[kk] * wv.y;
                acc0[c4 * 4 + 2] += hv0[kk] * wv.z;
                acc0[c4 * 4 + 3] += hv0[kk] * wv.w;
                acc1[c4 * 4 + 0] += hv1[kk] * wv.x;
                acc1[c4 * 4 + 1] += hv1[kk] * wv.y;
                acc1[c4 * 4 + 2] += hv1[kk] * wv.z;
                acc1[c4 * 4 + 3] += hv1[kk] * wv.w;
            }
        }
    }
    float* o0 = d_HW + (size_t)r0 * NC;
#pragma unroll
    for (int c4 = 0; c4 < NC / 4; c4++)
        *(float4*)(o0 + c4 * 4) = make_float4(acc0[c4 * 4], acc0[c4 * 4 + 1],
                                              acc0[c4 * 4 + 2], acc0[c4 * 4 + 3]);
    if (two) {
        float* o1 = d_HW + (size_t)r1 * NC;
#pragma unroll
        for (int c4 = 0; c4 < NC / 4; c4++)
            *(float4*)(o1 + c4 * 4) = make_float4(acc1[c4 * 4], acc1[c4 * 4 + 1],
                                                  acc1[c4 * 4 + 2], acc1[c4 * 4 + 3]);
    }
}

// ---------------- SpMM2: out = A @ d_HW + b2, warp per row (ELL) ----------------
__global__ __launch_bounds__(256) void k_spmm2(const float* __restrict__ b2,
                                               float* __restrict__ out) {
    int w = (blockIdx.x * blockDim.x + threadIdx.x) >> 5;
    int lane = threadIdx.x & 31;
    if (w >= NN) return;
    int cnt = d_deg[w];
    cnt = cnt < CAP ? cnt : CAP;
    const int*   cp = d_ecol + (size_t)w * CAP;
    const float* vp = d_eval + (size_t)w * CAP;
    float a0 = 0.f, a1 = 0.f;
    int i = 0;
    for (; i + 2 <= cnt; i += 2) {
        int   c0 = cp[i],   c1 = cp[i + 1];
        float v0 = vp[i],   v1 = vp[i + 1];
        const float* p0 = d_HW + (size_t)c0 * NC;
        const float* p1 = d_HW + (size_t)c1 * NC;
        float x0 = p0[lane];
        float x1 = p1[lane];
        float y0 = 0.f, y1 = 0.f;
        if (lane < 8) { y0 = p0[lane + 32]; y1 = p1[lane + 32]; }
        a0 += v0 * x0 + v1 * x1;
        a1 += v0 * y0 + v1 * y1;
    }
    if (i < cnt) {
        int   c = cp[i];
        float v = vp[i];
        const float* p = d_HW + (size_t)c * NC;
        a0 += v * p[lane];
        if (lane < 8) a1 += v * p[lane + 32];
    }
    float* o = out + (size_t)w * NC;
    o[lane] = a0 + b2[lane];
    if (lane < 8) o[lane + 32] = a1 + b2[lane + 32];
}

// ---------------- launch ----------------
extern "C" void kernel_launch(void* const* d_in, const int* in_sizes, int n_in,
                              void* d_out, int out_size) {
    const float* x   = (const float*)d_in[0];
    const float* W1  = (const float*)d_in[1];
    const float* b1  = (const float*)d_in[2];
    const float* W2  = (const float*)d_in[3];
    const float* b2  = (const float*)d_in[4];
    const int*   er  = (const int*)d_in[5];
    const int*   ec  = (const int*)d_in[6];
    const float* ev  = (const float*)d_in[7];
    int E = in_sizes[5];
    if (E > ECAP) E = ECAP;
    float* out = (float*)d_out;

    // kernel launch order: k_gemm1 at kernel index 3 (the profiled slot).
    k_zero<<<(NN + 511) / 512, 512>>>();                     // k0
    k_ell<<<(E + 255) / 256, 256>>>(er, ec, ev, E);          // k1
    k_prep<<<(NF * NH + 255) / 256, 256>>>(W1);              // k2
    k_gemm1<<<(NN + 127) / 128, 512>>>(x);                   // k3 <- PROFILED
    k_spmm1<<<(NN + 1) / 2, 256>>>(b1);                      // k4
    k_gemm2<<<(NN + 511) / 512, 256>>>(W2);                  // k5
    k_spmm2<<<(NN * 32 + 255) / 256, 256>>>(b2, out);        // k6
}

// round 14
// speedup vs baseline: 2.6073x; 1.1415x over previous
#include <cuda_runtime.h>
#include <cuda_fp16.h>
#include <cstdint>

#define NN 100000
#define NF 512
#define NH 256
#define NC 40
#define ECAP 1700000
#define CAP 96           // ELL max degree (true max ~45)

// ---------------- scratch (device-side access only) ----------------
__device__ __half2 d_XWh2[(size_t)NN * (NH / 2)];  // x@W1 in fp16 (51.2 MB)
__device__ __half  d_W1h[(size_t)NH * NF];         // W1^T fp16 [n][k] (256 KB)
__device__ float   d_H [(size_t)NN * NH];          // relu(A·XW + b1)
__device__ float   d_HW[(size_t)NN * NC];          // H @ W2
__device__ int     d_deg[NN];
__device__ int     d_ecol[(size_t)NN * CAP];
__device__ float   d_eval[(size_t)NN * CAP];

// ---------------- fused zero + W1 transpose ----------------
__global__ void k_prep(const float* __restrict__ W1) {
    int i = blockIdx.x * 256 + threadIdx.x;
    if (i < NF * NH) {
        int k = i >> 8;        // NH = 256
        int n = i & 255;
        d_W1h[n * NF + k] = __float2half_rn(W1[i]);
    }
    if (i < NN) d_deg[i] = 0;
}

__global__ void k_ell(const int* __restrict__ er, const int* __restrict__ ec,
                      const float* __restrict__ ev, int E) {
    int i = blockIdx.x * blockDim.x + threadIdx.x;
    if (i >= E) return;
    int r = er[i];
    int slot = atomicAdd(&d_deg[r], 1);
    if (slot < CAP) {
        d_ecol[(size_t)r * CAP + slot] = ec[i];
        d_eval[(size_t)r * CAP + slot] = ev[i];
    }
}

// ---------------- GEMM1 (fp16 mma + ldmatrix): XWh = fp16(x @ W1) ----------------
// 128x256 tile, 512 threads / 16 warps, warp tile 32x64, BK=32,
// mma.m16n8k16.f16 fp32-accum. Fragments via ldmatrix (LDSM):
// 80B row pitch -> 8-lane groups hit banks {0,80,32,112,64,16,96,48} mod 128,
// conflict-free.
__device__ __forceinline__ void ldsm_x4(uint32_t (&r)[4], uint32_t saddr) {
    asm volatile("ldmatrix.sync.aligned.m8n8.x4.shared.b16 {%0,%1,%2,%3}, [%4];"
                 : "=r"(r[0]), "=r"(r[1]), "=r"(r[2]), "=r"(r[3]) : "r"(saddr));
}
__device__ __forceinline__ void ldsm_x2(uint32_t& r0, uint32_t& r1, uint32_t saddr) {
    asm volatile("ldmatrix.sync.aligned.m8n8.x2.shared.b16 {%0,%1}, [%2];"
                 : "=r"(r0), "=r"(r1) : "r"(saddr));
}

__global__ __launch_bounds__(512) void k_gemm1(const float* __restrict__ X) {
    __shared__ __half As[128][40];    // [m][k], 80B pitch
    __shared__ __half Bt[256][40];    // [n][k], 80B pitch

    const int tid  = threadIdx.x;
    const int lane = tid & 31;
    const int wid  = tid >> 5;
    const int wm   = wid & 3;
    const int wn   = wid >> 2;
    const int tig  = lane & 3;
    const int m0   = blockIdx.x * 128;

    const uint32_t as_base = (uint32_t)__cvta_generic_to_shared(&As[0][0]);
    const uint32_t bt_base = (uint32_t)__cvta_generic_to_shared(&Bt[0][0]);

    // ldmatrix per-lane address components (constant across tiles):
    // A x4: row = wm*32 + mf*16 + (l&7) + ((l>>3)&1)*8 ; koff = ks*16 + (l>>4)*8
    const int a_row_l = (lane & 7) + ((lane >> 3) & 1) * 8;
    const int a_koff_l = (lane >> 4) * 8;
    // B x2: row n = n0 + (l&7) [lanes 0-15 used]; koff = ks*16 + ((l>>3)&1)*8
    const int b_row_l = lane & 7;
    const int b_koff_l = ((lane >> 3) & 1) * 8;

    float acc[2][8][4];
#pragma unroll
    for (int mf = 0; mf < 2; mf++)
#pragma unroll
        for (int nf = 0; nf < 8; nf++)
#pragma unroll
            for (int c = 0; c < 4; c++) acc[mf][nf][c] = 0.f;

    float4 ra[2];
    uint4  rb[2];

    auto loadreg = [&](int k0) {
#pragma unroll
        for (int p = 0; p < 2; p++) {
            int i = p * 512 + tid;
            int m = i >> 3, j = i & 7;
            int row = m0 + m;
            row = row < NN ? row : NN - 1;     // clamp; OOB rows never stored
            ra[p] = *(const float4*)(X + (size_t)row * NF + k0 + j * 4);
        }
#pragma unroll
        for (int p = 0; p < 2; p++) {
            int i = p * 512 + tid;
            int n = i >> 2, q = i & 3;
            rb[p] = *(const uint4*)(d_W1h + n * NF + k0 + q * 8);
        }
    };

    auto storesm = [&]() {
#pragma unroll
        for (int p = 0; p < 2; p++) {
            int i = p * 512 + tid;
            int m = i >> 3, j = i & 7;
            *(__half2*)&As[m][j * 4]     = __floats2half2_rn(ra[p].x, ra[p].y);
            *(__half2*)&As[m][j * 4 + 2] = __floats2half2_rn(ra[p].z, ra[p].w);
        }
#pragma unroll
        for (int p = 0; p < 2; p++) {
            int i = p * 512 + tid;
            int n = i >> 2, q = i & 3;
            *(uint4*)&Bt[n][q * 8] = rb[p];
        }
    };

    loadreg(0);

    const int NT = NF / 32;   // 16
    for (int t = 0; t < NT; t++) {
        __syncthreads();
        storesm();
        __syncthreads();
        if (t + 1 < NT) loadreg(32 * (t + 1));

#pragma unroll
        for (int ks = 0; ks < 2; ks++) {
            uint32_t a[2][4];
#pragma unroll
            for (int mf = 0; mf < 2; mf++) {
                int row = wm * 32 + mf * 16 + a_row_l;
                ldsm_x4(a[mf], as_base + (uint32_t)(row * 40 + ks * 16 + a_koff_l) * 2);
            }
#pragma unroll
            for (int nf = 0; nf < 8; nf++) {
                int n0 = wn * 64 + nf * 8;
                uint32_t b0, b1;
                ldsm_x2(b0, b1,
                        bt_base + (uint32_t)((n0 + b_row_l) * 40 + ks * 16 + b_koff_l) * 2);
#pragma unroll
                for (int mf = 0; mf < 2; mf++) {
                    asm volatile(
                        "mma.sync.aligned.m16n8k16.row.col.f32.f16.f16.f32 "
                        "{%0,%1,%2,%3}, {%4,%5,%6,%7}, {%8,%9}, {%0,%1,%2,%3};\n"
                        : "+f"(acc[mf][nf][0]), "+f"(acc[mf][nf][1]),
                          "+f"(acc[mf][nf][2]), "+f"(acc[mf][nf][3])
                        : "r"(a[mf][0]), "r"(a[mf][1]), "r"(a[mf][2]), "r"(a[mf][3]),
                          "r"(b0), "r"(b1));
                }
            }
        }
    }

    const int gid = lane >> 2;
#pragma unroll
    for (int mf = 0; mf < 2; mf++) {
#pragma unroll
        for (int nf = 0; nf < 8; nf++) {
            int row = m0 + wm * 32 + mf * 16 + gid;
            int col = wn * 64 + nf * 8 + 2 * tig;
            if (row < NN) {
                d_XWh2[(size_t)row * (NH / 2) + (col >> 1)] =
                    __floats2half2_rn(acc[mf][nf][0], acc[mf][nf][1]);
            }
            if (row + 8 < NN) {
                d_XWh2[(size_t)(row + 8) * (NH / 2) + (col >> 1)] =
                    __floats2half2_rn(acc[mf][nf][2], acc[mf][nf][3]);
            }
        }
    }
}

// ---------------- SpMM1: d_H = relu(A @ XWh + b1), WARP per row ----------------
// 32 lanes x 8 feats (one uint4 = 4 half2) per lane; whole 512B row per gather.
__global__ __launch_bounds__(256) void k_spmm1(const float* __restrict__ b1) {
    __shared__ int   sc[8][CAP];
    __shared__ float sv[8][CAP];
    const int lane = threadIdx.x & 31;
    const int wrp  = threadIdx.x >> 5;
    const int row  = blockIdx.x * 8 + wrp;
    if (row >= NN) return;

    int cnt = d_deg[row];
    cnt = cnt < CAP ? cnt : CAP;
    for (int j = lane; j < cnt; j += 32) {
        sc[wrp][j] = d_ecol[row * CAP + j];      // row*CAP < 9.6M -> int ok
        sv[wrp][j] = d_eval[row * CAP + j];
    }
    __syncwarp();

    const uint4* xb = (const uint4*)d_XWh2;      // 32 uint4 per node row
    float ax[8];
#pragma unroll
    for (int f = 0; f < 8; f++) ax[f] = 0.f;

    int j = 0;
    for (; j + 2 <= cnt; j += 2) {
        int   c0 = sc[wrp][j],  c1 = sc[wrp][j + 1];
        float v0 = sv[wrp][j],  v1 = sv[wrp][j + 1];
        uint4 u0 = __ldg(&xb[c0 * 32 + lane]);
        uint4 u1 = __ldg(&xb[c1 * 32 + lane]);
        float2 p;
        p = __half22float2(*(__half2*)&u0.x); ax[0] += v0 * p.x; ax[1] += v0 * p.y;
        p = __half22float2(*(__half2*)&u0.y); ax[2] += v0 * p.x; ax[3] += v0 * p.y;
        p = __half22float2(*(__half2*)&u0.z); ax[4] += v0 * p.x; ax[5] += v0 * p.y;
        p = __half22float2(*(__half2*)&u0.w); ax[6] += v0 * p.x; ax[7] += v0 * p.y;
        p = __half22float2(*(__half2*)&u1.x); ax[0] += v1 * p.x; ax[1] += v1 * p.y;
        p = __half22float2(*(__half2*)&u1.y); ax[2] += v1 * p.x; ax[3] += v1 * p.y;
        p = __half22float2(*(__half2*)&u1.z); ax[4] += v1 * p.x; ax[5] += v1 * p.y;
        p = __half22float2(*(__half2*)&u1.w); ax[6] += v1 * p.x; ax[7] += v1 * p.y;
    }
    if (j < cnt) {
        int   c = sc[wrp][j];
        float v = sv[wrp][j];
        uint4 u = __ldg(&xb[c * 32 + lane]);
        float2 p;
        p = __half22float2(*(__half2*)&u.x); ax[0] += v * p.x; ax[1] += v * p.y;
        p = __half22float2(*(__half2*)&u.y); ax[2] += v * p.x; ax[3] += v * p.y;
        p = __half22float2(*(__half2*)&u.z); ax[4] += v * p.x; ax[5] += v * p.y;
        p = __half22float2(*(__half2*)&u.w); ax[6] += v * p.x; ax[7] += v * p.y;
    }

    const float4* bb = (const float4*)(b1 + 8 * lane);
    float4 b0 = bb[0], b1v = bb[1];
    float4 o0 = make_float4(fmaxf(ax[0] + b0.x, 0.f), fmaxf(ax[1] + b0.y, 0.f),
                            fmaxf(ax[2] + b0.z, 0.f), fmaxf(ax[3] + b0.w, 0.f));
    float4 o1 = make_float4(fmaxf(ax[4] + b1v.x, 0.f), fmaxf(ax[5] + b1v.y, 0.f),
                            fmaxf(ax[6] + b1v.z, 0.f), fmaxf(ax[7] + b1v.w, 0.f));
    float* hp = d_H + (size_t)row * NH + 8 * lane;
    __stcs((float4*)hp, o0);
    __stcs((float4*)(hp + 4), o1);
}

// ---------------- GEMM2: d_HW = d_H @ W2 (2 rows/thread) ----------------
__global__ __launch_bounds__(256) void k_gemm2(const float* __restrict__ W2) {
    __shared__ float w2s[NH * NC];   // 40 KB
    for (int i = threadIdx.x; i < NH * NC; i += 256) w2s[i] = W2[i];
    __syncthreads();
    int r0 = blockIdx.x * 512 + threadIdx.x;
    int r1 = r0 + 256;
    if (r0 >= NN) return;
    bool two = (r1 < NN);
    float acc0[NC], acc1[NC];
#pragma unroll
    for (int c = 0; c < NC; c++) { acc0[c] = 0.f; acc1[c] = 0.f; }
    const float4* hp0 = (const float4*)(d_H + (size_t)r0 * NH);
    const float4* hp1 = (const float4*)(d_H + (size_t)(two ? r1 : r0) * NH);
#pragma unroll 2
    for (int k4 = 0; k4 < NH / 4; k4++) {
        float4 h0 = hp0[k4];
        float4 h1 = hp1[k4];
        float hv0[4] = {h0.x, h0.y, h0.z, h0.w};
        float hv1[4] = {h1.x, h1.y, h1.z, h1.w};
#pragma unroll
        for (int kk = 0; kk < 4; kk++) {
            const float* wrow = &w2s[(k4 * 4 + kk) * NC];
#pragma unroll
            for (int c4 = 0; c4 < NC / 4; c4++) {
                float4 wv = *(const float4*)(wrow + c4 * 4);
                acc0[c4 * 4 + 0] += hv0[kk] * wv.x;
                acc0[c4 * 4 + 1] += hv0[kk] * wv.y;
                acc0[c4 * 4 + 2] += hv0[kk] * wv.z;
                acc0[c4 * 4 + 3] += hv0[kk] * wv.w;
                acc1[c4 * 4 + 0] += hv1[kk] * wv.x;
                acc1[c4 * 4 + 1] += hv1[kk] * wv.y;
                acc1[c4 * 4 + 2] += hv1[kk] * wv.z;
                acc1[c4 * 4 + 3] += hv1[kk] * wv.w;
            }
        }
    }
    float* o0 = d_HW + (size_t)r0 * NC;
#pragma unroll
    for (int c4 = 0; c4 < NC / 4; c4++)
        *(float4*)(o0 + c4 * 4) = make_float4(acc0[c4 * 4], acc0[c4 * 4 + 1],
                                              acc0[c4 * 4 + 2], acc0[c4 * 4 + 3]);
    if (two) {
        float* o1 = d_HW + (size_t)r1 * NC;
#pragma unroll
        for (int c4 = 0; c4 < NC / 4; c4++)
            *(float4*)(o1 + c4 * 4) = make_float4(acc1[c4 * 4], acc1[c4 * 4 + 1],
                                                  acc1[c4 * 4 + 2], acc1[c4 * 4 + 3]);
    }
}

// ---------------- SpMM2: out = A @ d_HW + b2, warp per row (ELL) ----------------
__global__ __launch_bounds__(256) void k_spmm2(const float* __restrict__ b2,
                                               float* __restrict__ out) {
    int w = (blockIdx.x * blockDim.x + threadIdx.x) >> 5;
    int lane = threadIdx.x & 31;
    if (w >= NN) return;
    int cnt = d_deg[w];
    cnt = cnt < CAP ? cnt : CAP;
    const int*   cp = d_ecol + (size_t)w * CAP;
    const float* vp = d_eval + (size_t)w * CAP;
    float a0 = 0.f, a1 = 0.f;
    int i = 0;
    for (; i + 2 <= cnt; i += 2) {
        int   c0 = cp[i],   c1 = cp[i + 1];
        float v0 = vp[i],   v1 = vp[i + 1];
        const float* p0 = d_HW + (size_t)c0 * NC;
        const float* p1 = d_HW + (size_t)c1 * NC;
        float x0 = p0[lane];
        float x1 = p1[lane];
        float y0 = 0.f, y1 = 0.f;
        if (lane < 8) { y0 = p0[lane + 32]; y1 = p1[lane + 32]; }
        a0 += v0 * x0 + v1 * x1;
        a1 += v0 * y0 + v1 * y1;
    }
    if (i < cnt) {
        int   c = cp[i];
        float v = vp[i];
        const float* p = d_HW + (size_t)c * NC;
        a0 += v * p[lane];
        if (lane < 8) a1 += v * p[lane + 32];
    }
    float* o = out + (size_t)w * NC;
    o[lane] = a0 + b2[lane];
    if (lane < 8) o[lane + 32] = a1 + b2[lane + 32];
}

// ---------------- launch ----------------
extern "C" void kernel_launch(void* const* d_in, const int* in_sizes, int n_in,
                              void* d_out, int out_size) {
    const float* x   = (const float*)d_in[0];
    const float* W1  = (const float*)d_in[1];
    const float* b1  = (const float*)d_in[2];
    const float* W2  = (const float*)d_in[3];
    const float* b2  = (const float*)d_in[4];
    const int*   er  = (const int*)d_in[5];
    const int*   ec  = (const int*)d_in[6];
    const float* ev  = (const float*)d_in[7];
    int E = in_sizes[5];
    if (E > ECAP) E = ECAP;
    float* out = (float*)d_out;

    // kernel launch order: k_spmm1 at kernel index 3 (the profiled slot).
    k_prep<<<(NF * NH + 255) / 256, 256>>>(W1);              // k0 (zero + W1^T)
    k_ell<<<(E + 255) / 256, 256>>>(er, ec, ev, E);          // k1
    k_gemm1<<<(NN + 127) / 128, 512>>>(x);                   // k2
    k_spmm1<<<(NN + 7) / 8, 256>>>(b1);                      // k3 <- PROFILED
    k_gemm2<<<(NN + 511) / 512, 256>>>(W2);                  // k4
    k_spmm2<<<(NN * 32 + 255) / 256, 256>>>(b2, out);        // k5
}

// round 15
// speedup vs baseline: 3.3871x; 1.2991x over previous
#include <cuda_runtime.h>
#include <cuda_fp16.h>
#include <cstdint>

#define NN 100000
#define NF 512
#define NH 256
#define NC 40
#define ECAP 1700000
#define CAP 96           // ELL max degree (true max ~45)

// ---------------- scratch (device-side access only) ----------------
__device__ __half2 d_XWh2[(size_t)NN * (NH / 2)];  // x@W1 fp16 (51.2 MB)
__device__ __half  d_W1h[(size_t)NH * NF];         // W1^T fp16 [n][k]
__device__ __half  d_W2h[(size_t)NC * NH];         // W2^T fp16 [n][k] (20 KB)
__device__ __half2 d_Hh[(size_t)NN * (NH / 2)];    // relu(A·XW+b1) fp16 (51.2 MB)
__device__ float   d_HW[(size_t)NN * NC];          // H @ W2 (16 MB)
__device__ int     d_deg[NN];
__device__ int     d_ecol[(size_t)NN * CAP];
__device__ float   d_eval[(size_t)NN * CAP];

// ---------------- fused zero + weight transposes ----------------
__global__ void k_prep(const float* __restrict__ W1, const float* __restrict__ W2) {
    int i = blockIdx.x * 256 + threadIdx.x;
    if (i < NF * NH) {
        int k = i >> 8;        // NH = 256
        int n = i & 255;
        d_W1h[n * NF + k] = __float2half_rn(W1[i]);
    }
    if (i < NH * NC) {
        int k = i / NC;
        int n = i % NC;
        d_W2h[n * NH + k] = __float2half_rn(W2[i]);
    }
    if (i < NN) d_deg[i] = 0;
}

__global__ void k_ell(const int* __restrict__ er, const int* __restrict__ ec,
                      const float* __restrict__ ev, int lo, int hi) {
    int i = lo + blockIdx.x * blockDim.x + threadIdx.x;
    if (i >= hi) return;
    int r = er[i];
    int slot = atomicAdd(&d_deg[r], 1);
    if (slot < CAP) {
        d_ecol[(size_t)r * CAP + slot] = ec[i];
        d_eval[(size_t)r * CAP + slot] = ev[i];
    }
}

// ---------------- ldmatrix helpers ----------------
__device__ __forceinline__ void ldsm_x4(uint32_t (&r)[4], uint32_t saddr) {
    asm volatile("ldmatrix.sync.aligned.m8n8.x4.shared.b16 {%0,%1,%2,%3}, [%4];"
                 : "=r"(r[0]), "=r"(r[1]), "=r"(r[2]), "=r"(r[3]) : "r"(saddr));
}
__device__ __forceinline__ void ldsm_x2(uint32_t& r0, uint32_t& r1, uint32_t saddr) {
    asm volatile("ldmatrix.sync.aligned.m8n8.x2.shared.b16 {%0,%1}, [%2];"
                 : "=r"(r0), "=r"(r1) : "r"(saddr));
}
__device__ __forceinline__ void mma16816(float (&d)[4], const uint32_t (&a)[4],
                                         uint32_t b0, uint32_t b1) {
    asm volatile(
        "mma.sync.aligned.m16n8k16.row.col.f32.f16.f16.f32 "
        "{%0,%1,%2,%3}, {%4,%5,%6,%7}, {%8,%9}, {%0,%1,%2,%3};\n"
        : "+f"(d[0]), "+f"(d[1]), "+f"(d[2]), "+f"(d[3])
        : "r"(a[0]), "r"(a[1]), "r"(a[2]), "r"(a[3]), "r"(b0), "r"(b1));
}

// ---------------- GEMM1 (fp16 mma + ldmatrix): XWh = fp16(x @ W1) ----------------
__global__ __launch_bounds__(512) void k_gemm1(const float* __restrict__ X) {
    __shared__ __half As[128][40];    // [m][k], 80B pitch
    __shared__ __half Bt[256][40];    // [n][k], 80B pitch

    const int tid  = threadIdx.x;
    const int lane = tid & 31;
    const int wid  = tid >> 5;
    const int wm   = wid & 3;
    const int wn   = wid >> 2;
    const int tig  = lane & 3;
    const int m0   = blockIdx.x * 128;

    const uint32_t as_base = (uint32_t)__cvta_generic_to_shared(&As[0][0]);
    const uint32_t bt_base = (uint32_t)__cvta_generic_to_shared(&Bt[0][0]);

    const int a_row_l  = (lane & 7) + ((lane >> 3) & 1) * 8;
    const int a_koff_l = (lane >> 4) * 8;
    const int b_row_l  = lane & 7;
    const int b_koff_l = ((lane >> 3) & 1) * 8;

    float acc[2][8][4];
#pragma unroll
    for (int mf = 0; mf < 2; mf++)
#pragma unroll
        for (int nf = 0; nf < 8; nf++)
#pragma unroll
            for (int c = 0; c < 4; c++) acc[mf][nf][c] = 0.f;

    float4 ra[2];
    uint4  rb[2];

    auto loadreg = [&](int k0) {
#pragma unroll
        for (int p = 0; p < 2; p++) {
            int i = p * 512 + tid;
            int m = i >> 3, j = i & 7;
            int row = m0 + m;
            row = row < NN ? row : NN - 1;
            ra[p] = *(const float4*)(X + (size_t)row * NF + k0 + j * 4);
        }
#pragma unroll
        for (int p = 0; p < 2; p++) {
            int i = p * 512 + tid;
            int n = i >> 2, q = i & 3;
            rb[p] = *(const uint4*)(d_W1h + n * NF + k0 + q * 8);
        }
    };

    auto storesm = [&]() {
#pragma unroll
        for (int p = 0; p < 2; p++) {
            int i = p * 512 + tid;
            int m = i >> 3, j = i & 7;
            *(__half2*)&As[m][j * 4]     = __floats2half2_rn(ra[p].x, ra[p].y);
            *(__half2*)&As[m][j * 4 + 2] = __floats2half2_rn(ra[p].z, ra[p].w);
        }
#pragma unroll
        for (int p = 0; p < 2; p++) {
            int i = p * 512 + tid;
            int n = i >> 2, q = i & 3;
            *(uint4*)&Bt[n][q * 8] = rb[p];
        }
    };

    loadreg(0);

    const int NT = NF / 32;   // 16
    for (int t = 0; t < NT; t++) {
        __syncthreads();
        storesm();
        __syncthreads();
        if (t + 1 < NT) loadreg(32 * (t + 1));

#pragma unroll
        for (int ks = 0; ks < 2; ks++) {
            uint32_t a[2][4];
#pragma unroll
            for (int mf = 0; mf < 2; mf++) {
                int row = wm * 32 + mf * 16 + a_row_l;
                ldsm_x4(a[mf], as_base + (uint32_t)(row * 40 + ks * 16 + a_koff_l) * 2);
            }
#pragma unroll
            for (int nf = 0; nf < 8; nf++) {
                int n0 = wn * 64 + nf * 8;
                uint32_t b0, b1;
                ldsm_x2(b0, b1,
                        bt_base + (uint32_t)((n0 + b_row_l) * 40 + ks * 16 + b_koff_l) * 2);
#pragma unroll
                for (int mf = 0; mf < 2; mf++) mma16816(acc[mf][nf], a[mf], b0, b1);
            }
        }
    }

    const int gid = lane >> 2;
#pragma unroll
    for (int mf = 0; mf < 2; mf++) {
#pragma unroll
        for (int nf = 0; nf < 8; nf++) {
            int row = m0 + wm * 32 + mf * 16 + gid;
            int col = wn * 64 + nf * 8 + 2 * tig;
            if (row < NN) {
                d_XWh2[(size_t)row * (NH / 2) + (col >> 1)] =
                    __floats2half2_rn(acc[mf][nf][0], acc[mf][nf][1]);
            }
            if (row + 8 < NN) {
                d_XWh2[(size_t)(row + 8) * (NH / 2) + (col >> 1)] =
                    __floats2half2_rn(acc[mf][nf][2], acc[mf][nf][3]);
            }
        }
    }
}

// ---------------- SpMM1: d_Hh = fp16(relu(A @ XWh + b1)), WARP per row ----------------
__global__ __launch_bounds__(256) void k_spmm1(const float* __restrict__ b1) {
    __shared__ int   sc[8][CAP];
    __shared__ float sv[8][CAP];
    const int lane = threadIdx.x & 31;
    const int wrp  = threadIdx.x >> 5;
    const int row  = blockIdx.x * 8 + wrp;
    if (row >= NN) return;

    int cnt = d_deg[row];
    cnt = cnt < CAP ? cnt : CAP;
    for (int j = lane; j < cnt; j += 32) {
        sc[wrp][j] = d_ecol[row * CAP + j];
        sv[wrp][j] = d_eval[row * CAP + j];
    }
    __syncwarp();

    const uint4* xb = (const uint4*)d_XWh2;
    float ax[8];
#pragma unroll
    for (int f = 0; f < 8; f++) ax[f] = 0.f;

    int j = 0;
    for (; j + 2 <= cnt; j += 2) {
        int   c0 = sc[wrp][j],  c1 = sc[wrp][j + 1];
        float v0 = sv[wrp][j],  v1 = sv[wrp][j + 1];
        uint4 u0 = __ldg(&xb[c0 * 32 + lane]);
        uint4 u1 = __ldg(&xb[c1 * 32 + lane]);
        float2 p;
        p = __half22float2(*(__half2*)&u0.x); ax[0] += v0 * p.x; ax[1] += v0 * p.y;
        p = __half22float2(*(__half2*)&u0.y); ax[2] += v0 * p.x; ax[3] += v0 * p.y;
        p = __half22float2(*(__half2*)&u0.z); ax[4] += v0 * p.x; ax[5] += v0 * p.y;
        p = __half22float2(*(__half2*)&u0.w); ax[6] += v0 * p.x; ax[7] += v0 * p.y;
        p = __half22float2(*(__half2*)&u1.x); ax[0] += v1 * p.x; ax[1] += v1 * p.y;
        p = __half22float2(*(__half2*)&u1.y); ax[2] += v1 * p.x; ax[3] += v1 * p.y;
        p = __half22float2(*(__half2*)&u1.z); ax[4] += v1 * p.x; ax[5] += v1 * p.y;
        p = __half22float2(*(__half2*)&u1.w); ax[6] += v1 * p.x; ax[7] += v1 * p.y;
    }
    if (j < cnt) {
        int   c = sc[wrp][j];
        float v = sv[wrp][j];
        uint4 u = __ldg(&xb[c * 32 + lane]);
        float2 p;
        p = __half22float2(*(__half2*)&u.x); ax[0] += v * p.x; ax[1] += v * p.y;
        p = __half22float2(*(__half2*)&u.y); ax[2] += v * p.x; ax[3] += v * p.y;
        p = __half22float2(*(__half2*)&u.z); ax[4] += v * p.x; ax[5] += v * p.y;
        p = __half22float2(*(__half2*)&u.w); ax[6] += v * p.x; ax[7] += v * p.y;
    }

    const float4* bb = (const float4*)(b1 + 8 * lane);
    float4 b0 = bb[0], b1v = bb[1];
    uint4 o;
    *(__half2*)&o.x = __floats2half2_rn(fmaxf(ax[0] + b0.x, 0.f),
                                        fmaxf(ax[1] + b0.y, 0.f));
    *(__half2*)&o.y = __floats2half2_rn(fmaxf(ax[2] + b0.z, 0.f),
                                        fmaxf(ax[3] + b0.w, 0.f));
    *(__half2*)&o.z = __floats2half2_rn(fmaxf(ax[4] + b1v.x, 0.f),
                                        fmaxf(ax[5] + b1v.y, 0.f));
    *(__half2*)&o.w = __floats2half2_rn(fmaxf(ax[6] + b1v.z, 0.f),
                                        fmaxf(ax[7] + b1v.w, 0.f));
    __stcs((uint4*)((__half*)d_Hh + (size_t)row * NH + 8 * lane), o);
}

// ---------------- GEMM2 (fp16 mma): d_HW = Hh @ W2 ----------------
// 256 threads / 8 warps, 16 rows per warp (128 rows/block). A-frags loaded
// directly from gmem fp16 H (mapping identical to the verified scalar path);
// B-frags via ldsm_x2 from smem W2^T (pitch 264: 528 mod 128 = 16 ->
// 8 ldsm rows hit distinct 16B banks).
__global__ __launch_bounds__(256) void k_gemm2() {
    __shared__ __half W2s[NC][264];   // 40 x 264 halfs = 21120 B
    const int tid  = threadIdx.x;
    const int lane = tid & 31;
    const int wrp  = tid >> 5;
    const int gid  = lane >> 2;
    const int tig  = lane & 3;

    for (int i = tid; i < NC * 32; i += 256) {
        int n = i >> 5, q = i & 31;
        *(uint4*)&W2s[n][q * 8] = *(const uint4*)(d_W2h + n * NH + q * 8);
    }
    __syncthreads();

    const uint32_t w2base = (uint32_t)__cvta_generic_to_shared(&W2s[0][0]);
    const int b_row_l  = lane & 7;
    const int b_koff_l = ((lane >> 3) & 1) * 8;

    int r0 = blockIdx.x * 128 + wrp * 16;
    int rA = r0 + gid;
    int rB = rA + 8;
    int rAc = rA < NN ? rA : NN - 1;   // clamped load rows
    int rBc = rB < NN ? rB : NN - 1;
    const __half* H = (const __half*)d_Hh;

    float acc[5][4];
#pragma unroll
    for (int nf = 0; nf < 5; nf++)
#pragma unroll
        for (int c = 0; c < 4; c++) acc[nf][c] = 0.f;

#pragma unroll 4
    for (int ks = 0; ks < NH / 16; ks++) {
        int kc = ks * 16;
        const __half* pA = H + (size_t)rAc * NH + kc + 2 * tig;
        const __half* pB = H + (size_t)rBc * NH + kc + 2 * tig;
        uint32_t a[4];
        a[0] = *(const uint32_t*)pA;
        a[1] = *(const uint32_t*)pB;
        a[2] = *(const uint32_t*)(pA + 8);
        a[3] = *(const uint32_t*)(pB + 8);
#pragma unroll
        for (int nf = 0; nf < 5; nf++) {
            uint32_t b0, b1;
            ldsm_x2(b0, b1,
                    w2base + (uint32_t)((nf * 8 + b_row_l) * 264 + kc + b_koff_l) * 2);
            mma16816(acc[nf], a, b0, b1);
        }
    }

#pragma unroll
    for (int nf = 0; nf < 5; nf++) {
        int col = nf * 8 + 2 * tig;
        if (rA < NN)
            *(float2*)(d_HW + (size_t)rA * NC + col) = make_float2(acc[nf][0], acc[nf][1]);
        if (rB < NN)
            *(float2*)(d_HW + (size_t)rB * NC + col) = make_float2(acc[nf][2], acc[nf][3]);
    }
}

// ---------------- SpMM2: out = A @ d_HW + b2, warp per row (ELL) ----------------
__global__ __launch_bounds__(256) void k_spmm2(const float* __restrict__ b2,
                                               float* __restrict__ out) {
    int w = (blockIdx.x * blockDim.x + threadIdx.x) >> 5;
    int lane = threadIdx.x & 31;
    if (w >= NN) return;
    int cnt = d_deg[w];
    cnt = cnt < CAP ? cnt : CAP;
    const int*   cp = d_ecol + (size_t)w * CAP;
    const float* vp = d_eval + (size_t)w * CAP;
    float a0 = 0.f, a1 = 0.f;
    int i = 0;
    for (; i + 2 <= cnt; i += 2) {
        int   c0 = cp[i],   c1 = cp[i + 1];
        float v0 = vp[i],   v1 = vp[i + 1];
        const float* p0 = d_HW + (size_t)c0 * NC;
        const float* p1 = d_HW + (size_t)c1 * NC;
        float x0 = p0[lane];
        float x1 = p1[lane];
        float y0 = 0.f, y1 = 0.f;
        if (lane < 8) { y0 = p0[lane + 32]; y1 = p1[lane + 32]; }
        a0 += v0 * x0 + v1 * x1;
        a1 += v0 * y0 + v1 * y1;
    }
    if (i < cnt) {
        int   c = cp[i];
        float v = vp[i];
        const float* p = d_HW + (size_t)c * NC;
        a0 += v * p[lane];
        if (lane < 8) a1 += v * p[lane + 32];
    }
    float* o = out + (size_t)w * NC;
    o[lane] = a0 + b2[lane];
    if (lane < 8) o[lane + 32] = a1 + b2[lane + 32];
}

// ---------------- launch ----------------
extern "C" void kernel_launch(void* const* d_in, const int* in_sizes, int n_in,
                              void* d_out, int out_size) {
    const float* x   = (const float*)d_in[0];
    const float* W1  = (const float*)d_in[1];
    const float* b1  = (const float*)d_in[2];
    const float* W2  = (const float*)d_in[3];
    const float* b2  = (const float*)d_in[4];
    const int*   er  = (const int*)d_in[5];
    const int*   ec  = (const int*)d_in[6];
    const float* ev  = (const float*)d_in[7];
    int E = in_sizes[5];
    if (E > ECAP) E = ECAP;
    float* out = (float*)d_out;

    int Eh = E / 2;
    // kernel launch order: k_gemm1 at kernel index 3 (the profiled slot).
    k_prep<<<(NF * NH + 255) / 256, 256>>>(W1, W2);          // k0
    k_ell<<<(Eh + 255) / 256, 256>>>(er, ec, ev, 0, Eh);     // k1
    k_ell<<<(E - Eh + 255) / 256, 256>>>(er, ec, ev, Eh, E); // k2
    k_gemm1<<<(NN + 127) / 128, 512>>>(x);                   // k3 <- PROFILED
    k_spmm1<<<(NN + 7) / 8, 256>>>(b1);                      // k4
    k_gemm2<<<(NN + 127) / 128, 256>>>();                    // k5
    k_spmm2<<<(NN * 32 + 255) / 256, 256>>>(b2, out);        // k6
}